// round 16
// baseline (speedup 1.0000x reference)
#include <cuda_runtime.h>
#include <cuda_bf16.h>

// preds:   (16, 19, 512, 512) float32  = 79,691,776 elems
// targets: (16, 1024, 1024)   labels in [0,19) (delivered as int32)
// grid_size = 16 -> 32x32 cells per batch, 16x16 px each
//
// R15 structure (PDL overlap) with two tweaks:
//   k_presence: one warp per cell (4 int4 loads/lane, 16384 warps, 2048
//               blocks) -> 2x TLP vs R15; targets are L2-resident so the
//               kernel is latency-bound and scales with warp count.
//   k_loss:     E_STASH widened 6->8 so the mask-free phase (~11us of work)
//               fully covers presence even if PDL admits blocks late.
//   k_final:    verbatim.

#define N_ELEMS   79691776
#define N4        (N_ELEMS / 4)          // 19,922,944 float4s
#define N_CELLS   16384
#define LOSS_BLOCKS  2048
#define LOSS_THREADS 256
#define LOSS_STRIDE  (LOSS_BLOCKS * LOSS_THREADS)   // N4/STRIDE = 38 exactly
#define LOSS_ITERS   38
#define E_STASH      8

__device__ unsigned g_masks[N_CELLS];
__device__ double   g_partial[LOSS_BLOCKS];

__device__ __forceinline__ float ex2_(float x) { float r; asm("ex2.approx.f32 %0, %1;" : "=f"(r) : "f"(x)); return r; }
__device__ __forceinline__ float lg2_(float x) { float r; asm("lg2.approx.f32 %0, %1;" : "=f"(r) : "f"(x)); return r; }

// ---------------------------------------------------------------------------
// Kernel 1: per-cell class-presence bitmask (stride-2 NN downsample).
// One warp per cell: 4 independent int4 loads per lane (128 loads/warp).
// ---------------------------------------------------------------------------
__global__ void __launch_bounds__(256) k_presence(const int4* __restrict__ t4) {
    int cell = (blockIdx.x * blockDim.x + threadIdx.x) >> 5;   // 0..16383
    int lane = threadIdx.x & 31;
    int b    = cell >> 10;
    int rest = cell & 1023;
    int ch   = rest >> 5;
    int cw   = rest & 31;

    int base = (b << 18) + (ch << 13) + (cw << 3);

    int4 q[4];
#pragma unroll
    for (int k = 0; k < 4; ++k) {
        int e = lane + (k << 5);       // 0..127: 16 rows x 8 int4/row
        int i = e >> 3, jj = e & 7;
        q[k] = __ldg(&t4[base + (i << 9) + jj]);
    }
    unsigned m = 0;
#pragma unroll
    for (int k = 0; k < 4; ++k)
        m |= (1u << (q[k].x & 31)) | (1u << (q[k].z & 31));
    m = __reduce_or_sync(0xFFFFFFFFu, m);
    if (lane == 0) g_masks[cell] = m;
    cudaTriggerProgrammaticLaunchCompletion();
}

// mask-free: al += lg2(1+e^{-|x|}); aa += relu(x)
__device__ __forceinline__ void bce_free(float x, float& al, float& aa) {
    al += lg2_(1.0f + ex2_(fabsf(x) * -1.4426950408889634f));
    aa += fmaxf(x, 0.0f);
}
// masked: al-term + relu(se ? -x : x)
__device__ __forceinline__ void bce_acc(float x, unsigned sgn, float& al, float& aa) {
    float t = ex2_(fabsf(x) * -1.4426950408889634f);
    al += lg2_(1.0f + t);
    float y = __int_as_float(__float_as_int(x) ^ sgn);
    aa += fmaxf(y, 0.0f);
}

// ---------------------------------------------------------------------------
// Kernel 2: streaming loss; overlaps with k_presence via PDL.
// ---------------------------------------------------------------------------
__global__ void __launch_bounds__(LOSS_THREADS) k_loss(const float4* __restrict__ p4) {
    int tid = blockIdx.x * blockDim.x + threadIdx.x;
    int lin = tid << 2;
    int w   = lin & 511;
    int h   = (lin >> 9) & 511;
    int cellhw = ((h >> 4) << 5) + (w >> 4);   // loop-invariant
    int bc0 = lin >> 18;                       // b*19+c at iter 0; +8 per iter

    float al0 = 0.f, al1 = 0.f, aa0 = 0.f, aa1 = 0.f;

    // ---- phase 1: mask-free iters while k_presence drains ----
    float sx[E_STASH];
#pragma unroll
    for (int k = 0; k < E_STASH; ++k) {
        float4 v = __ldcs(p4 + tid + k * LOSS_STRIDE);
        bce_free(v.x, al0, aa0); bce_free(v.y, al1, aa1);
        bce_free(v.z, al0, aa0); bce_free(v.w, al1, aa1);
        sx[k] = (v.x + v.y) + (v.z + v.w);
    }

    // ---- wait for k_presence's writes to be visible ----
    cudaGridDependencySynchronize();

    // retro-fix stashed iters:  aa -= se_k * sum_x_k
#pragma unroll
    for (int k = 0; k < E_STASH; ++k) {
        int bc = bc0 + (k << 3);
        int b  = bc / 19;
        int c  = bc - b * 19;
        float se = (float)((g_masks[(b << 10) + cellhw] >> c) & 1u);
        aa0 = fmaf(-se, sx[k], aa0);
    }

    // ---- phase 2: masked loop ----
#pragma unroll 2
    for (int k = E_STASH; k < LOSS_ITERS; ++k) {
        float4 v = __ldcs(p4 + tid + k * LOSS_STRIDE);
        int bc = bc0 + (k << 3);
        int b  = bc / 19;
        int c  = bc - b * 19;
        unsigned mask = g_masks[(b << 10) + cellhw];
        unsigned sgn  = ((mask >> c) & 1u) << 31;
        bce_acc(v.x, sgn, al0, aa0);
        bce_acc(v.y, sgn, al1, aa1);
        bce_acc(v.z, sgn, al0, aa0);
        bce_acc(v.w, sgn, al1, aa1);
    }

    double acc = (double)(al0 + al1) * 0.6931471805599453 + (double)(aa0 + aa1);

    // deterministic block reduction
    __shared__ double smem[LOSS_THREADS / 32];
    for (int o = 16; o > 0; o >>= 1) acc += __shfl_down_sync(0xFFFFFFFFu, acc, o);
    if ((threadIdx.x & 31) == 0) smem[threadIdx.x >> 5] = acc;
    __syncthreads();
    if (threadIdx.x < (LOSS_THREADS / 32)) {
        double a = smem[threadIdx.x];
        for (int o = (LOSS_THREADS / 64); o > 0; o >>= 1)
            a += __shfl_down_sync(0xFFu, a, o);
        if (threadIdx.x == 0) g_partial[blockIdx.x] = a;
    }
}

// ---------------------------------------------------------------------------
// Kernel 3: final deterministic reduction -> mean.
// ---------------------------------------------------------------------------
__global__ void __launch_bounds__(256) k_final(float* __restrict__ out) {
    __shared__ double smem[8];
    double a = 0.0;
    for (int i = threadIdx.x; i < LOSS_BLOCKS; i += 256) a += g_partial[i];
    for (int o = 16; o > 0; o >>= 1) a += __shfl_down_sync(0xFFFFFFFFu, a, o);
    if ((threadIdx.x & 31) == 0) smem[threadIdx.x >> 5] = a;
    __syncthreads();
    if (threadIdx.x < 8) {
        double v = smem[threadIdx.x];
        for (int o = 4; o > 0; o >>= 1) v += __shfl_down_sync(0xFFu, v, o);
        if (threadIdx.x == 0) out[0] = (float)(v * (1.0 / (double)N_ELEMS));
    }
}

extern "C" void kernel_launch(void* const* d_in, const int* in_sizes, int n_in,
                              void* d_out, int out_size) {
    const float*  preds   = (const float*)d_in[0];
    const int4*   targets = (const int4*)d_in[1];
    float*        out     = (float*)d_out;

    k_presence<<<2048, 256>>>(targets);

    cudaLaunchConfig_t cfg = {};
    cfg.gridDim  = dim3(LOSS_BLOCKS);
    cfg.blockDim = dim3(LOSS_THREADS);
    cfg.stream   = 0;
    cudaLaunchAttribute attrs[1];
    attrs[0].id = cudaLaunchAttributeProgrammaticStreamSerialization;
    attrs[0].val.programmaticStreamSerializationAllowed = 1;
    cfg.attrs    = attrs;
    cfg.numAttrs = 1;
    cudaLaunchKernelEx(&cfg, k_loss, (const float4*)preds);

    k_final<<<1, 256>>>(out);
}

// round 17
// speedup vs baseline: 1.0452x; 1.0452x over previous
#include <cuda_runtime.h>
#include <cuda_bf16.h>

// preds:   (16, 19, 512, 512) float32  = 79,691,776 elems
// targets: (16, 1024, 1024)   labels in [0,19) (delivered as int32)
// grid_size = 16 -> 32x32 cells per batch, 16x16 px each
//
// PDL overlap, fixed mechanics:
//   k_presence: 512 blocks (whole grid resident in wave 1), 4 cells/warp,
//               TRIGGERS AT KERNEL ENTRY -> dependent loss grid launches
//               immediately and co-resides; visibility still guaranteed by
//               cudaGridDependencySynchronize (waits for grid completion).
//   k_loss:     phase 1 = 8 mask-free iters (overlaps presence), sync,
//               retro-fix -se*sum(x), phase 2 = masked loop. R16 verbatim.
//   k_final:    verbatim.

#define N_ELEMS   79691776
#define N4        (N_ELEMS / 4)          // 19,922,944 float4s
#define N_CELLS   16384
#define LOSS_BLOCKS  2048
#define LOSS_THREADS 256
#define LOSS_STRIDE  (LOSS_BLOCKS * LOSS_THREADS)   // N4/STRIDE = 38 exactly
#define LOSS_ITERS   38
#define E_STASH      8

__device__ unsigned g_masks[N_CELLS];
__device__ double   g_partial[LOSS_BLOCKS];

__device__ __forceinline__ float ex2_(float x) { float r; asm("ex2.approx.f32 %0, %1;" : "=f"(r) : "f"(x)); return r; }
__device__ __forceinline__ float lg2_(float x) { float r; asm("lg2.approx.f32 %0, %1;" : "=f"(r) : "f"(x)); return r; }

// ---------------------------------------------------------------------------
// Kernel 1: per-cell class-presence bitmask (stride-2 NN downsample).
// 512 blocks; one warp per 4 consecutive cells; 16 independent loads/thread.
// Trigger fires at entry so the dependent grid can launch and co-reside.
// ---------------------------------------------------------------------------
__global__ void __launch_bounds__(256) k_presence(const int4* __restrict__ t4) {
    cudaTriggerProgrammaticLaunchCompletion();

    int gwarp = (blockIdx.x * blockDim.x + threadIdx.x) >> 5;  // 0..4095
    int lane  = threadIdx.x & 31;
    int c0    = gwarp << 2;            // 4 consecutive cells (same batch/row)
    int b     = c0 >> 10;
    int rest  = c0 & 1023;
    int ch    = rest >> 5;
    int cw    = rest & 31;             // multiple of 4

    int base = (b << 18) + (ch << 13) + (cw << 3);

    int4 q[4][4];
#pragma unroll
    for (int k = 0; k < 4; ++k) {
        int e = lane + (k << 5);       // 0..127: 16 rows x 8 int4/row
        int i = e >> 3, jj = e & 7;
        int roff = (i << 9) + jj;
#pragma unroll
        for (int j = 0; j < 4; ++j)
            q[j][k] = __ldg(&t4[base + (j << 3) + roff]);
    }
    unsigned m[4];
#pragma unroll
    for (int j = 0; j < 4; ++j) {
        unsigned mm = 0;
#pragma unroll
        for (int k = 0; k < 4; ++k)
            mm |= (1u << (q[j][k].x & 31)) | (1u << (q[j][k].z & 31));
        m[j] = __reduce_or_sync(0xFFFFFFFFu, mm);
    }
    if (lane == 0)
        *reinterpret_cast<uint4*>(&g_masks[c0]) = make_uint4(m[0], m[1], m[2], m[3]);
}

// mask-free: al += lg2(1+e^{-|x|}); aa += relu(x)
__device__ __forceinline__ void bce_free(float x, float& al, float& aa) {
    al += lg2_(1.0f + ex2_(fabsf(x) * -1.4426950408889634f));
    aa += fmaxf(x, 0.0f);
}
// masked: al-term + relu(se ? -x : x)
__device__ __forceinline__ void bce_acc(float x, unsigned sgn, float& al, float& aa) {
    float t = ex2_(fabsf(x) * -1.4426950408889634f);
    al += lg2_(1.0f + t);
    float y = __int_as_float(__float_as_int(x) ^ sgn);
    aa += fmaxf(y, 0.0f);
}

// ---------------------------------------------------------------------------
// Kernel 2: streaming loss; co-resides with k_presence via PDL.
// ---------------------------------------------------------------------------
__global__ void __launch_bounds__(LOSS_THREADS) k_loss(const float4* __restrict__ p4) {
    int tid = blockIdx.x * blockDim.x + threadIdx.x;
    int lin = tid << 2;
    int w   = lin & 511;
    int h   = (lin >> 9) & 511;
    int cellhw = ((h >> 4) << 5) + (w >> 4);   // loop-invariant
    int bc0 = lin >> 18;                       // b*19+c at iter 0; +8 per iter

    float al0 = 0.f, al1 = 0.f, aa0 = 0.f, aa1 = 0.f;

    // ---- phase 1: mask-free iters while k_presence runs concurrently ----
    float sx[E_STASH];
#pragma unroll
    for (int k = 0; k < E_STASH; ++k) {
        float4 v = __ldcs(p4 + tid + k * LOSS_STRIDE);
        bce_free(v.x, al0, aa0); bce_free(v.y, al1, aa1);
        bce_free(v.z, al0, aa0); bce_free(v.w, al1, aa1);
        sx[k] = (v.x + v.y) + (v.z + v.w);
    }

    // ---- wait for k_presence's writes to be visible ----
    cudaGridDependencySynchronize();

    // retro-fix stashed iters:  aa -= se_k * sum_x_k
#pragma unroll
    for (int k = 0; k < E_STASH; ++k) {
        int bc = bc0 + (k << 3);
        int b  = bc / 19;
        int c  = bc - b * 19;
        float se = (float)((g_masks[(b << 10) + cellhw] >> c) & 1u);
        aa0 = fmaf(-se, sx[k], aa0);
    }

    // ---- phase 2: masked loop ----
#pragma unroll 2
    for (int k = E_STASH; k < LOSS_ITERS; ++k) {
        float4 v = __ldcs(p4 + tid + k * LOSS_STRIDE);
        int bc = bc0 + (k << 3);
        int b  = bc / 19;
        int c  = bc - b * 19;
        unsigned mask = g_masks[(b << 10) + cellhw];
        unsigned sgn  = ((mask >> c) & 1u) << 31;
        bce_acc(v.x, sgn, al0, aa0);
        bce_acc(v.y, sgn, al1, aa1);
        bce_acc(v.z, sgn, al0, aa0);
        bce_acc(v.w, sgn, al1, aa1);
    }

    double acc = (double)(al0 + al1) * 0.6931471805599453 + (double)(aa0 + aa1);

    // deterministic block reduction
    __shared__ double smem[LOSS_THREADS / 32];
    for (int o = 16; o > 0; o >>= 1) acc += __shfl_down_sync(0xFFFFFFFFu, acc, o);
    if ((threadIdx.x & 31) == 0) smem[threadIdx.x >> 5] = acc;
    __syncthreads();
    if (threadIdx.x < (LOSS_THREADS / 32)) {
        double a = smem[threadIdx.x];
        for (int o = (LOSS_THREADS / 64); o > 0; o >>= 1)
            a += __shfl_down_sync(0xFFu, a, o);
        if (threadIdx.x == 0) g_partial[blockIdx.x] = a;
    }
}

// ---------------------------------------------------------------------------
// Kernel 3: final deterministic reduction -> mean.
// ---------------------------------------------------------------------------
__global__ void __launch_bounds__(256) k_final(float* __restrict__ out) {
    __shared__ double smem[8];
    double a = 0.0;
    for (int i = threadIdx.x; i < LOSS_BLOCKS; i += 256) a += g_partial[i];
    for (int o = 16; o > 0; o >>= 1) a += __shfl_down_sync(0xFFFFFFFFu, a, o);
    if ((threadIdx.x & 31) == 0) smem[threadIdx.x >> 5] = a;
    __syncthreads();
    if (threadIdx.x < 8) {
        double v = smem[threadIdx.x];
        for (int o = 4; o > 0; o >>= 1) v += __shfl_down_sync(0xFFu, v, o);
        if (threadIdx.x == 0) out[0] = (float)(v * (1.0 / (double)N_ELEMS));
    }
}

extern "C" void kernel_launch(void* const* d_in, const int* in_sizes, int n_in,
                              void* d_out, int out_size) {
    const float*  preds   = (const float*)d_in[0];
    const int4*   targets = (const int4*)d_in[1];
    float*        out     = (float*)d_out;

    k_presence<<<512, 256>>>(targets);

    cudaLaunchConfig_t cfg = {};
    cfg.gridDim  = dim3(LOSS_BLOCKS);
    cfg.blockDim = dim3(LOSS_THREADS);
    cfg.stream   = 0;
    cudaLaunchAttribute attrs[1];
    attrs[0].id = cudaLaunchAttributeProgrammaticStreamSerialization;
    attrs[0].val.programmaticStreamSerializationAllowed = 1;
    cfg.attrs    = attrs;
    cfg.numAttrs = 1;
    cudaLaunchKernelEx(&cfg, k_loss, (const float4*)preds);

    k_final<<<1, 256>>>(out);
}